// round 15
// baseline (speedup 1.0000x reference)
#include <cuda_runtime.h>
#include <cuda_fp16.h>
#include <cstdint>

// Problem dims
#define BB 128
#define SS 2048
#define HH 512
#define AA 512

// ---------------- device scratch (no allocations allowed) ----------------
__device__ __align__(1024) __half g_Wt[AA * HH];            // W^T as [A][H] (K contiguous)
__device__ __align__(16) __half g_Xh[(size_t)BB * SS * HH]; // fp16 copy of X (written by GEMM)
__device__ __align__(16) float g_vu[BB * SS];               // unnormalized exp(vu)
__device__ float g_Z[BB];                                   // per-batch softmax partition sums
__device__ unsigned g_cnt[BB];                              // per-batch arrival counters (wrap 16)

// ---------------- smem layout for GEMM kernel (3 CTAs/SM target) ----------------
// A stages: 2 x 18432 ; B stages: 2 x 18432 ; bu/red/sv union: 4096 -> total 77824
// 3 x 77824 = 233472 = full 228KB SM smem budget (exact fit)
#define T_STRIDE 144u
#define T_STAGE  18432u
#define OFF_A    0u
#define OFF_B    36864u
#define OFF_BU   73728u
#define SMEM_TOTAL 77824

__device__ __forceinline__ uint32_t smem_u32(const void* p) {
    uint32_t a;
    asm("{ .reg .u64 t; cvta.to.shared.u64 t, %1; cvt.u32.u64 %0, t; }" : "=r"(a) : "l"(p));
    return a;
}

__device__ __forceinline__ void ldsm_x4(uint32_t* r, uint32_t addr) {
    asm volatile("ldmatrix.sync.aligned.m8n8.x4.shared.b16 {%0,%1,%2,%3}, [%4];"
                 : "=r"(r[0]), "=r"(r[1]), "=r"(r[2]), "=r"(r[3]) : "r"(addr));
}

__device__ __forceinline__ void mma16816_f16(uint32_t* c, const uint32_t* a, uint32_t b0, uint32_t b1) {
    asm volatile("mma.sync.aligned.m16n8k16.row.col.f16.f16.f16.f16 "
                 "{%0,%1}, {%2,%3,%4,%5}, {%6,%7}, {%0,%1};"
                 : "+r"(c[0]), "+r"(c[1])
                 : "r"(a[0]), "r"(a[1]), "r"(a[2]), "r"(a[3]), "r"(b0), "r"(b1));
}

__device__ __forceinline__ float tanh_fast(float x) {
    float t;
    asm("tanh.approx.f32 %0, %1;" : "=f"(t) : "f"(x));
    return t;
}

// issue cp.asyncs for iteration `it` into stage it&1 (ONE commit group):
//   B chunk always: W^T rows [nt*128,+128), k [kc*64,+64)
//   A chunk when nt>0: from g_Xh rows [row_base,+128), k [kc*64,+64)
__device__ __forceinline__ void cp_stage(uint32_t sb, int it, size_t row_base, int tid) {
    const int nt = it >> 3, kc = it & 7;
    const uint32_t stg = (uint32_t)(it & 1) * T_STAGE;
    // B
    {
        const char* src_base = reinterpret_cast<const char*>(g_Wt)
                             + (size_t)(nt * 128) * 1024 + (size_t)kc * 128;
        #pragma unroll
        for (int i = 0; i < 4; i++) {
            int idx = tid + i * 256;
            int r = idx >> 3, c = idx & 7;
            uint32_t dst = sb + OFF_B + stg + (uint32_t)r * T_STRIDE + (uint32_t)c * 16;
            const void* src = src_base + (size_t)r * 1024 + c * 16;
            asm volatile("cp.async.cg.shared.global [%0], [%1], 16;" :: "r"(dst), "l"(src));
        }
    }
    // A (re-stage fp16 copy) when not first N pass
    if (nt > 0) {
        const char* src_base = reinterpret_cast<const char*>(g_Xh)
                             + (row_base * 512 + (size_t)kc * 64) * 2;
        #pragma unroll
        for (int i = 0; i < 4; i++) {
            int idx = tid + i * 256;
            int r = idx >> 3, c = idx & 7;
            uint32_t dst = sb + OFF_A + stg + (uint32_t)r * T_STRIDE + (uint32_t)c * 16;
            const void* src = src_base + (size_t)r * 1024 + c * 16;
            asm volatile("cp.async.cg.shared.global [%0], [%1], 16;" :: "r"(dst), "l"(src));
        }
    }
    asm volatile("cp.async.commit_group;" ::: "memory");
}

// ---------------- fused GEMM(X@W) + tanh + dot(u) -> exp(vu) ; fp16 X copy ;
// ---------------- max-free softmax partials + exp-weighted sum ; elected normalize tail ----
// CTA: 128 M x 512 N x 512 K.  4 N-passes of 128.  Warps: 4(M) x 2(N), warp tile 32x64, f16 acc.
__global__ void __launch_bounds__(256, 3)
gemm_vu_kernel(const float* __restrict__ X,
               const float* __restrict__ bias,
               const float* __restrict__ u,
               float* __restrict__ out_bh,
               float* __restrict__ out_alphas)
{
    extern __shared__ char smem[];
    const uint32_t sb = smem_u32(smem);
    const int tid  = threadIdx.x;
    const int lane = tid & 31;
    const int wid  = tid >> 5;
    const int wm   = wid >> 1;         // 0..3 (M warp)
    const int wn   = wid & 1;          // 0..1 (N warp)
    const int t4   = lane & 3;
    const int g    = lane >> 2;
    const size_t row_base = (size_t)blockIdx.x * 128;
    const int batch = blockIdx.x >> 4;           // 16 CTAs per batch

    // interleaved {bias, u/sqrt(A)} table
    float2* bu_s = reinterpret_cast<float2*>(smem + OFF_BU);
    for (int i = tid; i < 512; i += 256)
        bu_s[i] = make_float2(bias[i], u[i] * 0.04419417382415922f);

    // prologue: B chunk 0 (A chunk 0 is staged manually in iteration 0)
    cp_stage(sb, 0, row_base, tid);

    const float4* Xv = reinterpret_cast<const float4*>(X) + row_base * 128;

    // ldmatrix lane address components (both tiles use T_STRIDE chunk layout)
    const uint32_t a_lane_off = (uint32_t)(wm * 32 + (lane & 15)) * T_STRIDE
                              + (uint32_t)((lane >> 4) * 8) * 2;
    const uint32_t b_row  = (uint32_t)((lane & 7) + ((lane >> 4) << 3));
    const uint32_t b_koff = (uint32_t)(((lane >> 3) & 1) * 8);
    const uint32_t b_lane_off = (uint32_t)(wn * 64 + b_row) * T_STRIDE + b_koff * 2;

    uint32_t acc[2][8][2];      // fp16x2 accumulators
    float vu_p[4] = {0.f, 0.f, 0.f, 0.f};

    #pragma unroll 1
    for (int it = 0; it < 32; it++) {
        const int nt = it >> 3, kc = it & 7;

        if (it + 1 < 32) {
            cp_stage(sb, it + 1, row_base, tid);
            asm volatile("cp.async.wait_group 1;" ::: "memory");
        } else {
            asm volatile("cp.async.wait_group 0;" ::: "memory");
        }

        // first N pass: manually stage A chunk kc (fp32 X -> fp16 smem + g_Xh)
        if (nt == 0) {
            #pragma unroll
            for (int i = 0; i < 8; i++) {
                int idx = tid + i * 256;
                int r = idx >> 4, c4 = idx & 15;
                float4 v = Xv[(size_t)r * 128 + kc * 16 + c4];
                __half2 lo = __float22half2_rn(make_float2(v.x, v.y));
                __half2 hi = __float22half2_rn(make_float2(v.z, v.w));
                uint2 p;
                p.x = *reinterpret_cast<uint32_t*>(&lo);
                p.y = *reinterpret_cast<uint32_t*>(&hi);
                *reinterpret_cast<uint2*>(smem + OFF_A + (uint32_t)(it & 1) * T_STAGE
                                          + (uint32_t)r * T_STRIDE + (uint32_t)c4 * 8) = p;
                *reinterpret_cast<uint2*>(&g_Xh[(row_base + r) * 512 + kc * 64 + c4 * 4]) = p;
            }
        }
        __syncthreads();

        if (kc == 0) {
            #pragma unroll
            for (int mi = 0; mi < 2; mi++)
                #pragma unroll
                for (int ni = 0; ni < 8; ni++) {
                    acc[mi][ni][0] = 0u;
                    acc[mi][ni][1] = 0u;
                }
        }

        const uint32_t ast = sb + OFF_A + (uint32_t)(it & 1) * T_STAGE + a_lane_off;
        const uint32_t bst = sb + OFF_B + (uint32_t)(it & 1) * T_STAGE + b_lane_off;

        #pragma unroll
        for (int ks = 0; ks < 4; ks++) {
            const uint32_t koff = (uint32_t)(ks * 16) * 2;
            uint32_t a0[4], a1[4];
            ldsm_x4(a0, ast + koff);
            ldsm_x4(a1, ast + 16 * T_STRIDE + koff);
            uint32_t b[4][4];
            #pragma unroll
            for (int nb = 0; nb < 4; nb++)
                ldsm_x4(b[nb], bst + (uint32_t)(nb * 16) * T_STRIDE + koff);
            #pragma unroll
            for (int ni = 0; ni < 8; ni++) {
                const int nb = ni >> 1, hi = (ni & 1) * 2;
                mma16816_f16(acc[0][ni], a0, b[nb][hi], b[nb][hi + 1]);
                mma16816_f16(acc[1][ni], a1, b[nb][hi], b[nb][hi + 1]);
            }
        }

        // epilogue for this 128-wide N tile
        if (kc == 7) {
            #pragma unroll
            for (int mi = 0; mi < 2; mi++)
                #pragma unroll
                for (int ni = 0; ni < 8; ni++) {
                    const int n0 = nt * 128 + wn * 64 + ni * 8 + t4 * 2;
                    float4 bu = *reinterpret_cast<const float4*>(&bu_s[n0]);
                    float2 f0 = __half22float2(*reinterpret_cast<__half2*>(&acc[mi][ni][0]));
                    float2 f1 = __half22float2(*reinterpret_cast<__half2*>(&acc[mi][ni][1]));
                    float t0 = tanh_fast(f0.x + bu.x);
                    float t1 = tanh_fast(f0.y + bu.z);
                    float t2 = tanh_fast(f1.x + bu.x);
                    float t3 = tanh_fast(f1.y + bu.z);
                    vu_p[2 * mi]     = fmaf(t0, bu.y, fmaf(t1, bu.w, vu_p[2 * mi]));
                    vu_p[2 * mi + 1] = fmaf(t2, bu.y, fmaf(t3, bu.w, vu_p[2 * mi + 1]));
                }
        }
        __syncthreads();
    }

    // reduce vu partials: over t4 lanes, then over the 2 N warps via smem
    // bu_s is dead after the last mainloop epilogue -> red lives at OFF_BU+1024
    #pragma unroll
    for (int j = 0; j < 4; j++) {
        vu_p[j] += __shfl_xor_sync(0xFFFFFFFFu, vu_p[j], 1);
        vu_p[j] += __shfl_xor_sync(0xFFFFFFFFu, vu_p[j], 2);
    }
    float* red = reinterpret_cast<float*>(smem + OFF_BU + 1024);
    if (t4 == 0) {
        #pragma unroll
        for (int mi = 0; mi < 2; mi++)
            #pragma unroll
            for (int rh = 0; rh < 2; rh++)
                red[wn * 128 + wm * 32 + mi * 16 + rh * 8 + g] = vu_p[2 * mi + rh];
    }
    __syncthreads();

    // ---- max-free softmax partials: e = exp(vu); Z partial; exp-weighted sum into out ----
    // |vu| <= ~0.15 by construction (tanh-bounded dot with u/sqrt(A)), so exp is safe.
    float* sv   = reinterpret_cast<float*>(smem + OFF_BU);        // 128 e values (512 B)
    float* sred = reinterpret_cast<float*>(smem + OFF_BU + 512);  // warp Z partials
    if (tid < 128) {
        float vu = red[tid] + red[128 + tid];
        float e = __expf(vu);
        g_vu[row_base + tid] = e;      // unnormalized exp
        sv[tid] = e;
        // warp-level Z partial
        float z = e;
        z += __shfl_xor_sync(0xFFFFFFFFu, z, 16);
        z += __shfl_xor_sync(0xFFFFFFFFu, z, 8);
        z += __shfl_xor_sync(0xFFFFFFFFu, z, 4);
        z += __shfl_xor_sync(0xFFFFFFFFu, z, 2);
        z += __shfl_xor_sync(0xFFFFFFFFu, z, 1);
        if (lane == 0) sred[wid] = z;
    }
    __syncthreads();
    if (tid == 0)
        atomicAdd(&g_Z[batch], (sred[0] + sred[1]) + (sred[2] + sred[3]));

    // partial out: rows split in 2 halves of 64; each thread owns one float4 h-column
    {
        const int rh = tid >> 7;           // 0 or 1
        const int c4 = tid & 127;          // float4 column index (h = c4*4..+3)
        const uint2* Xh = reinterpret_cast<const uint2*>(g_Xh)
                        + (row_base + (size_t)rh * 64) * 128 + c4;
        float4 a4 = make_float4(0.f, 0.f, 0.f, 0.f);
        #pragma unroll 8
        for (int s = 0; s < 64; s++) {
            float e = sv[rh * 64 + s];
            uint2 v = Xh[(size_t)s * 128];
            float2 f0 = __half22float2(*reinterpret_cast<__half2*>(&v.x));
            float2 f1 = __half22float2(*reinterpret_cast<__half2*>(&v.y));
            a4.x = fmaf(e, f0.x, a4.x);
            a4.y = fmaf(e, f0.y, a4.y);
            a4.z = fmaf(e, f1.x, a4.z);
            a4.w = fmaf(e, f1.y, a4.w);
        }
        float4* comb = reinterpret_cast<float4*>(smem + OFF_A);   // stages dead
        if (rh) comb[c4] = a4;
        __syncthreads();
        if (!rh) {
            float4 o = comb[c4];
            o.x += a4.x; o.y += a4.y; o.z += a4.z; o.w += a4.w;
            float* dst = out_bh + (size_t)batch * HH + c4 * 4;
            atomicAdd(dst + 0, o.x);
            atomicAdd(dst + 1, o.y);
            atomicAdd(dst + 2, o.z);
            atomicAdd(dst + 3, o.w);
        }
    }

    // ---- last-CTA-per-batch election -> normalize alphas and out for this batch ----
    __syncthreads();                 // all atomics above issued by every thread
    __threadfence();                 // order g_Z / g_vu / out atomics before arrival
    __shared__ unsigned s_elect;
    if (tid == 0)
        s_elect = (atomicInc(&g_cnt[batch], 15u) == 15u) ? 1u : 0u;   // wraps -> replay-safe
    __syncthreads();
    if (s_elect) {
        const float inv = 1.0f / (g_Z[batch] + 1e-10f);
        const float* vub = &g_vu[(size_t)batch * SS];
        float* ab = out_alphas + (size_t)batch * SS;
        for (int i = tid; i < SS; i += 256)
            ab[i] = vub[i] * inv;
        float* ob = out_bh + (size_t)batch * HH;
        for (int i = tid; i < HH; i += 256)
            ob[i] *= inv;
    }
}

// ---------------- W transpose + fp16 convert ; zero out[B,H] and g_Z ----------------
__global__ void __launch_bounds__(256)
convert_w_kernel(const float* __restrict__ W, float* __restrict__ out)
{
    int idx = blockIdx.x * 256 + threadIdx.x;   // 262144
    int h = idx >> 9, a = idx & 511;
    g_Wt[a * HH + h] = __float2half(W[idx]);
    if (idx < BB * HH)
        out[idx] = 0.0f;
    if (idx < BB)
        g_Z[idx] = 0.0f;
}

// ---------------- launcher ----------------
extern "C" void kernel_launch(void* const* d_in, const int* in_sizes, int n_in,
                              void* d_out, int out_size)
{
    const float* X    = (const float*)d_in[0];   // [B,S,H]
    const float* W    = (const float*)d_in[1];   // [H,A]
    const float* bias = (const float*)d_in[2];   // [A]
    const float* u    = (const float*)d_in[3];   // [A]

    float* out    = (float*)d_out;               // [B,H] first
    float* alphas = out + BB * HH;               // then [B,S]

    cudaFuncSetAttribute(gemm_vu_kernel,
                         cudaFuncAttributeMaxDynamicSharedMemorySize, SMEM_TOTAL);

    convert_w_kernel<<<1024, 256>>>(W, out);
    gemm_vu_kernel<<<(BB * SS) / 128, 256, SMEM_TOTAL>>>(X, bias, u, out, alphas);
}

// round 16
// speedup vs baseline: 1.1259x; 1.1259x over previous
#include <cuda_runtime.h>
#include <cuda_fp16.h>
#include <cstdint>

// Problem dims
#define BB 128
#define SS 2048
#define HH 512
#define AA 512

// ---------------- device scratch (no allocations allowed) ----------------
__device__ __align__(1024) __half g_Wt[AA * HH];            // W^T as [A][H] (K contiguous)
__device__ __align__(16) __half g_Xh[(size_t)BB * SS * HH]; // fp16 copy of X (written by GEMM)
__device__ __align__(16) float g_vu[BB * SS];               // unnormalized exp(vu)
__device__ float g_Z[BB];                                   // per-batch softmax partition sums
__device__ unsigned g_cnt[BB];                              // per-batch arrival counters (wrap 16)

// ---------------- smem layout for GEMM kernel (3 CTAs/SM) ----------------
// A stages: 2 x 18432 ; B stages: 2 x 18432 ; aux (bu half2 / red / sv union): 2048
// total 75776 ; 3 x (75776 + 1024 reserve) = 230400 <= 233472 SM smem -> 3 CTAs/SM
#define T_STRIDE 144u
#define T_STAGE  18432u
#define OFF_A    0u
#define OFF_B    36864u
#define OFF_BU   73728u
#define SMEM_TOTAL 75776

__device__ __forceinline__ uint32_t smem_u32(const void* p) {
    uint32_t a;
    asm("{ .reg .u64 t; cvta.to.shared.u64 t, %1; cvt.u32.u64 %0, t; }" : "=r"(a) : "l"(p));
    return a;
}

__device__ __forceinline__ void ldsm_x4(uint32_t* r, uint32_t addr) {
    asm volatile("ldmatrix.sync.aligned.m8n8.x4.shared.b16 {%0,%1,%2,%3}, [%4];"
                 : "=r"(r[0]), "=r"(r[1]), "=r"(r[2]), "=r"(r[3]) : "r"(addr));
}

__device__ __forceinline__ void mma16816_f16(uint32_t* c, const uint32_t* a, uint32_t b0, uint32_t b1) {
    asm volatile("mma.sync.aligned.m16n8k16.row.col.f16.f16.f16.f16 "
                 "{%0,%1}, {%2,%3,%4,%5}, {%6,%7}, {%0,%1};"
                 : "+r"(c[0]), "+r"(c[1])
                 : "r"(a[0]), "r"(a[1]), "r"(a[2]), "r"(a[3]), "r"(b0), "r"(b1));
}

__device__ __forceinline__ float tanh_fast(float x) {
    float t;
    asm("tanh.approx.f32 %0, %1;" : "=f"(t) : "f"(x));
    return t;
}

// issue cp.asyncs for iteration `it` into stage it&1 (ONE commit group):
//   B chunk always: W^T rows [nt*128,+128), k [kc*64,+64)
//   A chunk when nt>0: from g_Xh rows [row_base,+128), k [kc*64,+64)
__device__ __forceinline__ void cp_stage(uint32_t sb, int it, size_t row_base, int tid) {
    const int nt = it >> 3, kc = it & 7;
    const uint32_t stg = (uint32_t)(it & 1) * T_STAGE;
    // B
    {
        const char* src_base = reinterpret_cast<const char*>(g_Wt)
                             + (size_t)(nt * 128) * 1024 + (size_t)kc * 128;
        #pragma unroll
        for (int i = 0; i < 4; i++) {
            int idx = tid + i * 256;
            int r = idx >> 3, c = idx & 7;
            uint32_t dst = sb + OFF_B + stg + (uint32_t)r * T_STRIDE + (uint32_t)c * 16;
            const void* src = src_base + (size_t)r * 1024 + c * 16;
            asm volatile("cp.async.cg.shared.global [%0], [%1], 16;" :: "r"(dst), "l"(src));
        }
    }
    // A (re-stage fp16 copy) when not first N pass
    if (nt > 0) {
        const char* src_base = reinterpret_cast<const char*>(g_Xh)
                             + (row_base * 512 + (size_t)kc * 64) * 2;
        #pragma unroll
        for (int i = 0; i < 4; i++) {
            int idx = tid + i * 256;
            int r = idx >> 3, c = idx & 7;
            uint32_t dst = sb + OFF_A + stg + (uint32_t)r * T_STRIDE + (uint32_t)c * 16;
            const void* src = src_base + (size_t)r * 1024 + c * 16;
            asm volatile("cp.async.cg.shared.global [%0], [%1], 16;" :: "r"(dst), "l"(src));
        }
    }
    asm volatile("cp.async.commit_group;" ::: "memory");
}

// ---------------- fused GEMM(X@W) + tanh + dot(u) -> exp(vu) ; fp16 X copy ;
// ---------------- max-free softmax partials + exp-weighted sum ; elected normalize tail ----
// CTA: 128 M x 512 N x 512 K.  4 N-passes of 128.  Warps: 4(M) x 2(N), warp tile 32x64, f16 acc.
__global__ void __launch_bounds__(256, 3)
gemm_vu_kernel(const float* __restrict__ X,
               const float* __restrict__ bias,
               const float* __restrict__ u,
               float* __restrict__ out_bh,
               float* __restrict__ out_alphas)
{
    extern __shared__ char smem[];
    const uint32_t sb = smem_u32(smem);
    const int tid  = threadIdx.x;
    const int lane = tid & 31;
    const int wid  = tid >> 5;
    const int wm   = wid >> 1;         // 0..3 (M warp)
    const int wn   = wid & 1;          // 0..1 (N warp)
    const int t4   = lane & 3;
    const int g    = lane >> 2;
    const size_t row_base = (size_t)blockIdx.x * 128;
    const int batch = blockIdx.x >> 4;           // 16 CTAs per batch

    // half2 {bias, u/sqrt(A)} table (2048 B)
    __half2* bu_s = reinterpret_cast<__half2*>(smem + OFF_BU);
    for (int i = tid; i < 512; i += 256)
        bu_s[i] = __floats2half2_rn(bias[i], u[i] * 0.04419417382415922f);

    // prologue: B chunk 0 (A chunk 0 is staged manually in iteration 0)
    cp_stage(sb, 0, row_base, tid);

    const float4* Xv = reinterpret_cast<const float4*>(X) + row_base * 128;

    // ldmatrix lane address components (both tiles use T_STRIDE chunk layout)
    const uint32_t a_lane_off = (uint32_t)(wm * 32 + (lane & 15)) * T_STRIDE
                              + (uint32_t)((lane >> 4) * 8) * 2;
    const uint32_t b_row  = (uint32_t)((lane & 7) + ((lane >> 4) << 3));
    const uint32_t b_koff = (uint32_t)(((lane >> 3) & 1) * 8);
    const uint32_t b_lane_off = (uint32_t)(wn * 64 + b_row) * T_STRIDE + b_koff * 2;

    uint32_t acc[2][8][2];      // fp16x2 accumulators
    float vu_p[4] = {0.f, 0.f, 0.f, 0.f};

    #pragma unroll 1
    for (int it = 0; it < 32; it++) {
        const int nt = it >> 3, kc = it & 7;

        if (it + 1 < 32) {
            cp_stage(sb, it + 1, row_base, tid);
            asm volatile("cp.async.wait_group 1;" ::: "memory");
        } else {
            asm volatile("cp.async.wait_group 0;" ::: "memory");
        }

        // first N pass: manually stage A chunk kc (fp32 X -> fp16 smem + g_Xh)
        if (nt == 0) {
            #pragma unroll
            for (int i = 0; i < 8; i++) {
                int idx = tid + i * 256;
                int r = idx >> 4, c4 = idx & 15;
                float4 v = Xv[(size_t)r * 128 + kc * 16 + c4];
                __half2 lo = __float22half2_rn(make_float2(v.x, v.y));
                __half2 hi = __float22half2_rn(make_float2(v.z, v.w));
                uint2 p;
                p.x = *reinterpret_cast<uint32_t*>(&lo);
                p.y = *reinterpret_cast<uint32_t*>(&hi);
                *reinterpret_cast<uint2*>(smem + OFF_A + (uint32_t)(it & 1) * T_STAGE
                                          + (uint32_t)r * T_STRIDE + (uint32_t)c4 * 8) = p;
                *reinterpret_cast<uint2*>(&g_Xh[(row_base + r) * 512 + kc * 64 + c4 * 4]) = p;
            }
        }
        __syncthreads();

        if (kc == 0) {
            #pragma unroll
            for (int mi = 0; mi < 2; mi++)
                #pragma unroll
                for (int ni = 0; ni < 8; ni++) {
                    acc[mi][ni][0] = 0u;
                    acc[mi][ni][1] = 0u;
                }
        }

        const uint32_t ast = sb + OFF_A + (uint32_t)(it & 1) * T_STAGE + a_lane_off;
        const uint32_t bst = sb + OFF_B + (uint32_t)(it & 1) * T_STAGE + b_lane_off;

        #pragma unroll
        for (int ks = 0; ks < 4; ks++) {
            const uint32_t koff = (uint32_t)(ks * 16) * 2;
            uint32_t a0[4], a1[4];
            ldsm_x4(a0, ast + koff);
            ldsm_x4(a1, ast + 16 * T_STRIDE + koff);
            uint32_t b[4][4];
            #pragma unroll
            for (int nb = 0; nb < 4; nb++)
                ldsm_x4(b[nb], bst + (uint32_t)(nb * 16) * T_STRIDE + koff);
            #pragma unroll
            for (int ni = 0; ni < 8; ni++) {
                const int nb = ni >> 1, hi = (ni & 1) * 2;
                mma16816_f16(acc[0][ni], a0, b[nb][hi], b[nb][hi + 1]);
                mma16816_f16(acc[1][ni], a1, b[nb][hi], b[nb][hi + 1]);
            }
        }

        // epilogue for this 128-wide N tile
        if (kc == 7) {
            #pragma unroll
            for (int mi = 0; mi < 2; mi++)
                #pragma unroll
                for (int ni = 0; ni < 8; ni++) {
                    const int n0 = nt * 128 + wn * 64 + ni * 8 + t4 * 2;
                    float2 bu0 = __half22float2(bu_s[n0]);       // {bias, u'} for col n0
                    float2 bu1 = __half22float2(bu_s[n0 + 1]);   // {bias, u'} for col n0+1
                    float2 f0 = __half22float2(*reinterpret_cast<__half2*>(&acc[mi][ni][0]));
                    float2 f1 = __half22float2(*reinterpret_cast<__half2*>(&acc[mi][ni][1]));
                    float t0 = tanh_fast(f0.x + bu0.x);
                    float t1 = tanh_fast(f0.y + bu1.x);
                    float t2 = tanh_fast(f1.x + bu0.x);
                    float t3 = tanh_fast(f1.y + bu1.x);
                    vu_p[2 * mi]     = fmaf(t0, bu0.y, fmaf(t1, bu1.y, vu_p[2 * mi]));
                    vu_p[2 * mi + 1] = fmaf(t2, bu0.y, fmaf(t3, bu1.y, vu_p[2 * mi + 1]));
                }
        }
        __syncthreads();
    }

    // reduce vu partials: over t4 lanes, then over the 2 N warps via smem
    // bu_s is dead after the last mainloop epilogue -> red lives at OFF_BU+1024
    #pragma unroll
    for (int j = 0; j < 4; j++) {
        vu_p[j] += __shfl_xor_sync(0xFFFFFFFFu, vu_p[j], 1);
        vu_p[j] += __shfl_xor_sync(0xFFFFFFFFu, vu_p[j], 2);
    }
    float* red = reinterpret_cast<float*>(smem + OFF_BU + 1024);   // 1024 B
    if (t4 == 0) {
        #pragma unroll
        for (int mi = 0; mi < 2; mi++)
            #pragma unroll
            for (int rh = 0; rh < 2; rh++)
                red[wn * 128 + wm * 32 + mi * 16 + rh * 8 + g] = vu_p[2 * mi + rh];
    }
    __syncthreads();

    // ---- max-free softmax partials: e = exp(vu); Z partial; exp-weighted sum into out ----
    // |vu| <= ~0.15 by construction (tanh-bounded dot with u/sqrt(A)), so exp is safe.
    float* sv   = reinterpret_cast<float*>(smem + OFF_BU);        // 128 e values (512 B)
    float* sred = reinterpret_cast<float*>(smem + OFF_BU + 512);  // warp Z partials
    if (tid < 128) {
        float vu = red[tid] + red[128 + tid];
        float e = __expf(vu);
        g_vu[row_base + tid] = e;      // unnormalized exp
        sv[tid] = e;
        // warp-level Z partial
        float z = e;
        z += __shfl_xor_sync(0xFFFFFFFFu, z, 16);
        z += __shfl_xor_sync(0xFFFFFFFFu, z, 8);
        z += __shfl_xor_sync(0xFFFFFFFFu, z, 4);
        z += __shfl_xor_sync(0xFFFFFFFFu, z, 2);
        z += __shfl_xor_sync(0xFFFFFFFFu, z, 1);
        if (lane == 0) sred[wid] = z;
    }
    __syncthreads();
    if (tid == 0)
        atomicAdd(&g_Z[batch], (sred[0] + sred[1]) + (sred[2] + sred[3]));

    // partial out: rows split in 2 halves of 64; each thread owns one float4 h-column
    {
        const int rh = tid >> 7;           // 0 or 1
        const int c4 = tid & 127;          // float4 column index (h = c4*4..+3)
        const uint2* Xh = reinterpret_cast<const uint2*>(g_Xh)
                        + (row_base + (size_t)rh * 64) * 128 + c4;
        float4 a4 = make_float4(0.f, 0.f, 0.f, 0.f);
        #pragma unroll 8
        for (int s = 0; s < 64; s++) {
            float e = sv[rh * 64 + s];
            uint2 v = Xh[(size_t)s * 128];
            float2 f0 = __half22float2(*reinterpret_cast<__half2*>(&v.x));
            float2 f1 = __half22float2(*reinterpret_cast<__half2*>(&v.y));
            a4.x = fmaf(e, f0.x, a4.x);
            a4.y = fmaf(e, f0.y, a4.y);
            a4.z = fmaf(e, f1.x, a4.z);
            a4.w = fmaf(e, f1.y, a4.w);
        }
        float4* comb = reinterpret_cast<float4*>(smem + OFF_A);   // stages dead
        if (rh) comb[c4] = a4;
        __syncthreads();
        if (!rh) {
            float4 o = comb[c4];
            o.x += a4.x; o.y += a4.y; o.z += a4.z; o.w += a4.w;
            float* dst = out_bh + (size_t)batch * HH + c4 * 4;
            atomicAdd(dst + 0, o.x);
            atomicAdd(dst + 1, o.y);
            atomicAdd(dst + 2, o.z);
            atomicAdd(dst + 3, o.w);
        }
    }

    // ---- last-CTA-per-batch election -> normalize alphas and out for this batch ----
    __syncthreads();                 // all atomics above issued by every thread
    __threadfence();                 // order g_Z / g_vu / out atomics before arrival
    __shared__ unsigned s_elect;
    if (tid == 0)
        s_elect = (atomicInc(&g_cnt[batch], 15u) == 15u) ? 1u : 0u;   // wraps -> replay-safe
    __syncthreads();
    if (s_elect) {
        const float inv = 1.0f / (g_Z[batch] + 1e-10f);
        const float* vub = &g_vu[(size_t)batch * SS];
        float* ab = out_alphas + (size_t)batch * SS;
        for (int i = tid; i < SS; i += 256)
            ab[i] = vub[i] * inv;
        float* ob = out_bh + (size_t)batch * HH;
        for (int i = tid; i < HH; i += 256)
            ob[i] *= inv;
    }
}

// ---------------- W transpose + fp16 convert ; zero out[B,H] and g_Z ----------------
__global__ void __launch_bounds__(256)
convert_w_kernel(const float* __restrict__ W, float* __restrict__ out)
{
    int idx = blockIdx.x * 256 + threadIdx.x;   // 262144
    int h = idx >> 9, a = idx & 511;
    g_Wt[a * HH + h] = __float2half(W[idx]);
    if (idx < BB * HH)
        out[idx] = 0.0f;
    if (idx < BB)
        g_Z[idx] = 0.0f;
}

// ---------------- launcher ----------------
extern "C" void kernel_launch(void* const* d_in, const int* in_sizes, int n_in,
                              void* d_out, int out_size)
{
    const float* X    = (const float*)d_in[0];   // [B,S,H]
    const float* W    = (const float*)d_in[1];   // [H,A]
    const float* bias = (const float*)d_in[2];   // [A]
    const float* u    = (const float*)d_in[3];   // [A]

    float* out    = (float*)d_out;               // [B,H] first
    float* alphas = out + BB * HH;               // then [B,S]

    cudaFuncSetAttribute(gemm_vu_kernel,
                         cudaFuncAttributeMaxDynamicSharedMemorySize, SMEM_TOTAL);

    convert_w_kernel<<<1024, 256>>>(W, out);
    gemm_vu_kernel<<<(BB * SS) / 128, 256, SMEM_TOTAL>>>(X, bias, u, out, alphas);
}